// round 13
// baseline (speedup 1.0000x reference)
#include <cuda_runtime.h>

#define NQ 22
#define DIM (1u << 22)

// ---------------- device scratch (static: no allocation) ----------------
__device__ float g_psi0[DIM];
__device__ float g_psi1[DIM];
__device__ float g_sums[110];
__device__ unsigned g_done;

__device__ __forceinline__ float wred(float v) {
    #pragma unroll
    for (int o = 16; o; o >>= 1) v += __shfl_xor_sync(0xffffffffu, v, o);
    return v;
}
__device__ __forceinline__ float sgnx(float v, unsigned sb) {
    return __uint_as_float(__float_as_uint(v) ^ sb);
}
__device__ __forceinline__ float sf8(const float* y) {
    return ((y[0]-y[1]) - (y[2]-y[3])) - ((y[4]-y[5]) - (y[6]-y[7]));
}
__device__ __forceinline__ float sf4(const float* y) {
    return (y[0]-y[1]) - (y[2]-y[3]);
}

// ---------------- kernel 1: state gen + layer-2 RY on bits 12..0 ----------------
__global__ void __launch_bounds__(512, 2) k_genA(const float* __restrict__ theta) {
    __shared__ float s[8192];
    __shared__ float cs0s[NQ][2];
    __shared__ float cs1s[NQ][2];
    int bx = blockIdx.x;
    int st = bx >> 9;
    unsigned base = (unsigned)(bx & 511) << 13;
    int t = threadIdx.x;
    int lane = t & 31;

    // block 0 zeroes the global accumulators + completion counter (replay-safe)
    if (bx == 0) {
        if (t < 110) g_sums[t] = 0.f;
        if (t == 110) g_done = 0u;
    }

    if (t < NQ) {
        float h0 = 0.5f * theta[t];
        cs0s[t][0] = cosf(h0); cs0s[t][1] = sinf(h0);
        float h1 = 0.5f * theta[NQ + t];
        cs1s[t][0] = cosf(h1); cs1s[t][1] = sinf(h1);
    }
    __syncthreads();

    // build swizzled product tables in smem
    #pragma unroll
    for (int rep = 0; rep < 4; rep++) {
        int v = t + rep * 512;
        float ph = 1.f;
        #pragma unroll
        for (int k = 0; k < 11; k++)
            ph *= cs0s[10 - k][(v >> k) & 1];
        float pl = 1.f;
        #pragma unroll
        for (int k = 1; k < 11; k++)
            pl *= cs0s[21 - k][(v >> k) & 1];
        int b0 = v & 1;
        float f21 = st ? (b0 ? cs0s[21][0] : -cs0s[21][1]) : cs0s[21][b0];
        unsigned sw = (unsigned)v ^ (((unsigned)v >> 5) & 31u);
        s[sw] = ph;
        s[2048 + sw] = pl * f21;
    }
    __syncthreads();

    float r[16];
    #pragma unroll
    for (int i = 0; i < 16; i++) {
        unsigned y = base + (unsigned)(t * 16 + i);
        unsigned x = (y ^ (y >> 1)) ^ ((y & 1u) * 0x300000u);
        unsigned hi = x >> 11, lo = x & 2047u;
        r[i] = s[hi ^ ((hi >> 5) & 31u)] * s[2048 + (lo ^ ((lo >> 5) & 31u))];
    }

    #pragma unroll
    for (int br = 0; br < 4; br++) {
        int q = 21 - br;
        float c = cs1s[q][0], sn = cs1s[q][1];
        #pragma unroll
        for (int i0 = 0; i0 < 16; i0++) if (!(i0 & (1 << br))) {
            int i1 = i0 | (1 << br);
            float a0 = r[i0], a1 = r[i1];
            r[i0] = c * a0 - sn * a1;
            r[i1] = sn * a0 + c * a1;
        }
    }
    #pragma unroll
    for (int lb = 0; lb < 5; lb++) {
        int q = 17 - lb;
        float c = cs1s[q][0], sn = cs1s[q][1];
        float ss = (lane & (1 << lb)) ? sn : -sn;
        #pragma unroll
        for (int i = 0; i < 16; i++) {
            float p = __shfl_xor_sync(0xffffffffu, r[i], 1 << lb);
            r[i] = fmaf(ss, p, c * r[i]);
        }
    }
    __syncthreads();

    #pragma unroll
    for (int i = 0; i < 16; i++) {
        unsigned o = (unsigned)(t * 16 + i);
        s[o ^ ((o >> 5) & 31u)] = r[i];
    }
    __syncthreads();
    #pragma unroll
    for (int j = 0; j < 16; j++) {
        unsigned o = ((unsigned)j << 9) | (unsigned)t;
        r[j] = s[o ^ ((o >> 5) & 31u)];
    }
    #pragma unroll
    for (int bj = 0; bj < 4; bj++) {
        int q = 12 - bj;
        float c = cs1s[q][0], sn = cs1s[q][1];
        #pragma unroll
        for (int j0 = 0; j0 < 16; j0++) if (!(j0 & (1 << bj))) {
            int j1 = j0 | (1 << bj);
            float a0 = r[j0], a1 = r[j1];
            r[j0] = c * a0 - sn * a1;
            r[j1] = sn * a0 + c * a1;
        }
    }
    float* __restrict__ g = st ? g_psi1 : g_psi0;
    #pragma unroll
    for (int j = 0; j < 16; j++)
        g[base + ((unsigned)j << 9) + (unsigned)t] = r[j];
}

// ---------------- kernel 2: layer-2 RY on bits 13..21, register-blocked ----------------
__global__ void __launch_bounds__(512, 2) k_passB(const float* __restrict__ theta) {
    __shared__ float s[512 * 17];
    __shared__ float cs1s[NQ][2];
    int bx = blockIdx.x;
    int st = bx >> 9;
    unsigned mid = (unsigned)(bx & 511) << 4;
    float* __restrict__ g = st ? g_psi1 : g_psi0;
    int t = threadIdx.x;
    int lane = t & 31, w = t >> 5;   // w = 0..15

    if (t < NQ) {
        float h1 = 0.5f * theta[NQ + t];
        cs1s[t][0] = cosf(h1); cs1s[t][1] = sinf(h1);
    }

    const float4* G4 = (const float4*)g;
    for (int v = t; v < 2048; v += 512) {
        int hi = v >> 2, q = v & 3;
        float4 d = G4[((unsigned)hi << 11) + (mid >> 2) + (unsigned)q];
        int sb = hi * 17 + q * 4;
        s[sb + 0] = d.x; s[sb + 1] = d.y; s[sb + 2] = d.z; s[sb + 3] = d.w;
    }
    __syncthreads();

    float r[16];
    #pragma unroll
    for (int j = 0; j < 16; j++)
        r[j] = s[((j << 5) | lane) * 17 + w];

    #pragma unroll
    for (int lb = 0; lb < 5; lb++) {
        int q = 8 - lb;
        float c = cs1s[q][0], sn = cs1s[q][1];
        float ss = (lane & (1 << lb)) ? sn : -sn;
        #pragma unroll
        for (int j = 0; j < 16; j++) {
            float p = __shfl_xor_sync(0xffffffffu, r[j], 1 << lb);
            r[j] = fmaf(ss, p, c * r[j]);
        }
    }
    #pragma unroll
    for (int bj = 0; bj < 4; bj++) {
        int q = 3 - bj;
        float c = cs1s[q][0], sn = cs1s[q][1];
        #pragma unroll
        for (int j0 = 0; j0 < 16; j0++) if (!(j0 & (1 << bj))) {
            int j1 = j0 | (1 << bj);
            float a0 = r[j0], a1 = r[j1];
            r[j0] = c * a0 - sn * a1;
            r[j1] = sn * a0 + c * a1;
        }
    }
    #pragma unroll
    for (int j = 0; j < 16; j++)
        s[((j << 5) | lane) * 17 + w] = r[j];
    __syncthreads();

    float4* GW4 = (float4*)g;
    for (int v = t; v < 2048; v += 512) {
        int hi = v >> 2, q = v & 3;
        int sb = hi * 17 + q * 4;
        float4 d = make_float4(s[sb + 0], s[sb + 1], s[sb + 2], s[sb + 3]);
        GW4[((unsigned)hi << 11) + (mid >> 2) + (unsigned)q] = d;
    }
}

// ---------------- kernel 3: register-blocked Pauli reductions + fused finale ----------------
// Slot layout (85 real slots, warp-only signs deferred to column phase):
//   0 Te, 1 Tf ; 2+k Ze_k, 11+k Zf_k (k=0..8)
//   m20:20..22 m19:23..25 m18:26..28 m17:29..31          (group 0)
//   m16:32..34 m15:35..37 m14:38..40 m13:41..43
//   m12:44,45 m11:46,47 m10:48,49 (ad,a01 only)
//   m0:50..53  m1:54..56 m2:57..59 m3:60..62  [63 spare] (group 1)
//   m4:64..66 .. m9:79..81  m21:82..85  [86..95 spare]   (group 2)
// Deferred (column phase, written to sacc[0][86..94]):
//   86..88 Ze k=9,10,11 ; 89..91 Zf k=9,10,11 ; 92..94 W for m=12,11,10
__global__ void __launch_bounds__(256, 3) k_reduce(float* __restrict__ out) {
    __shared__ float s0[4096];
    __shared__ float s1[4096];
    __shared__ float sacc[8][96];
    __shared__ unsigned slast;
    unsigned tile = blockIdx.x;
    unsigned base = tile << 12;
    int t = threadIdx.x, w = t >> 5, lane = t & 31;
    int c = t;

    float acc[96];
    #pragma unroll
    for (int k = 0; k < 96; k++) acc[k] = 0.f;

    float r0[16], r1[16];
    {
        const float4* G0 = (const float4*)(g_psi0 + base);
        const float4* G1 = (const float4*)(g_psi1 + base);
        float4* S0 = (float4*)s0;
        float4* S1 = (float4*)s1;
        #pragma unroll
        for (int q = 0; q < 4; q++) {
            float4 a = G0[c * 4 + q]; S0[c * 4 + q] = a;
            r0[q*4+0] = a.x; r0[q*4+1] = a.y; r0[q*4+2] = a.z; r0[q*4+3] = a.w;
            float4 b = G1[c * 4 + q]; S1[c * 4 + q] = b;
            r1[q*4+0] = b.x; r1[q*4+1] = b.y; r1[q*4+2] = b.z; r1[q*4+3] = b.w;
        }
    }
    unsigned H = ((unsigned)(__popc(t & 0xFF) & 1)) << 31;

    #define TREE32(BS) { \
        _Pragma("unroll") \
        for (int off = 16; off >= 1; off >>= 1) { \
            _Pragma("unroll") \
            for (int k = 0; k < off; k++) { \
                float send = (lane & off) ? acc[(BS)+k] : acc[(BS)+k+off]; \
                float recv = __shfl_xor_sync(0xffffffffu, send, off); \
                acc[(BS)+k] = ((lane & off) ? acc[(BS)+k+off] : acc[(BS)+k]) + recv; \
            } \
        } \
        sacc[w][(BS) + lane] = acc[(BS)]; \
    }

    // Z sums: k=0..3 -> D0..D3 signed by H; k=4..8 -> T signed by popc(t>>(k-4)).
    // k=9,10,11 (warp-only sign) deferred.
    #define ZFOLD(EXPR, IDXBASE, TOTIDX) { \
        float x[16]; \
        _Pragma("unroll") for (int i = 0; i < 16; i++) x[i] = (EXPR); \
        float s1a[8], d0[8]; \
        _Pragma("unroll") for (int j = 0; j < 8; j++) { \
            s1a[j] = x[2*j] + x[2*j+1]; d0[j] = x[2*j] - x[2*j+1]; } \
        float D0 = sf8(d0), D1 = sf8(s1a); \
        float s2[4]; \
        _Pragma("unroll") for (int j = 0; j < 4; j++) s2[j] = s1a[2*j] + s1a[2*j+1]; \
        float D2 = sf4(s2); \
        float s3a = s2[0] + s2[1], s3b = s2[2] + s2[3]; \
        float D3 = s3a - s3b, T = s3a + s3b; \
        acc[(IDXBASE)+0] = sgnx(D0, H); \
        acc[(IDXBASE)+1] = sgnx(D1, H); \
        acc[(IDXBASE)+2] = sgnx(D2, H); \
        acc[(IDXBASE)+3] = sgnx(D3, H); \
        _Pragma("unroll") for (int k = 4; k < 9; k++) { \
            unsigned hk = ((unsigned)(__popc((unsigned)t >> (k-4)) & 1)) << 31; \
            acc[(IDXBASE)+k] = sgnx(T, hk); } \
        acc[TOTIDX] = T; }

    ZFOLD(r0[i]*r0[i] - r1[i]*r1[i], 2, 0)
    ZFOLD(r0[i]*r1[i], 11, 1)
    #undef ZFOLD

    #define INREG(SLOT, MSK, PB) { \
        float ad = 0.f, us = 0.f, wr = 0.f; \
        _Pragma("unroll") for (int i = 0; i < 16; i++) { \
            float p0 = r0[i ^ (MSK)], p1 = r1[i ^ (MSK)]; \
            ad += r0[i]*p0 - r1[i]*p1; \
            float u = r0[i]*p1; us += u; \
            if (__popc(i >> (PB)) & 1) wr -= u; else wr += u; } \
        acc[(SLOT)+0] = ad; acc[(SLOT)+1] = us; acc[(SLOT)+2] = sgnx(wr, H); }
    INREG(20, 3, 1)    // m=20
    INREG(23, 6, 2)    // m=19
    INREG(26, 12, 3)   // m=18
    #undef INREG

    #define SHFM(SLOT, MM, LX, IX) { \
        float ad = 0.f, us = 0.f; \
        _Pragma("unroll") for (int i = 0; i < 16; i++) { \
            float p0 = __shfl_xor_sync(0xffffffffu, r0[i ^ (IX)], (LX)); \
            float p1 = __shfl_xor_sync(0xffffffffu, r1[i ^ (IX)], (LX)); \
            ad += r0[i]*p0 - r1[i]*p1; us += r0[i]*p1; } \
        unsigned hs = ((unsigned)(__popc((unsigned)t >> (21-(MM)-4)) & 1)) << 31; \
        acc[(SLOT)+0] = ad; acc[(SLOT)+1] = us; acc[(SLOT)+2] = sgnx(us, hs); }
    SHFM(29, 17, 1, 8)
    TREE32(0)          // group 0 complete
    SHFM(32, 16, 3, 0)
    SHFM(35, 15, 6, 0)
    SHFM(38, 14, 12, 0)
    SHFM(41, 13, 24, 0)
    #undef SHFM

    __syncthreads();

    // smem masks m=12,11,10: ad + a01 only (W deferred, warp-only sign)
    #define SMEMM(SLOT, CX) { \
        float ad = 0.f, us = 0.f; \
        const float4* S04 = (const float4*)s0; \
        const float4* S14 = (const float4*)s1; \
        _Pragma("unroll") for (int q = 0; q < 4; q++) { \
            float4 a = S04[(c ^ (CX)) * 4 + q], b = S14[(c ^ (CX)) * 4 + q]; \
            float pa[4] = {a.x, a.y, a.z, a.w}; \
            float pb[4] = {b.x, b.y, b.z, b.w}; \
            _Pragma("unroll") for (int z = 0; z < 4; z++) { \
                int i = q*4 + z; \
                ad += r0[i]*pa[z] - r1[i]*pb[z]; us += r0[i]*pb[z]; } } \
        acc[(SLOT)+0] = ad; acc[(SLOT)+1] = us; }
    SMEMM(44, 0x30)   // m=12
    SMEMM(46, 0x60)   // m=11
    SMEMM(48, 0xC0)   // m=10
    #undef SMEMM

    #define CROSSM(SLOT, DH, CH, SWAP, DOW, CONDBIT) \
    if (!(base & (CONDBIT))) { \
        float ad = 0.f, U = 0.f, V = 0.f, wr = 0.f; \
        const float4* P0 = (const float4*)(g_psi0 + (base ^ (DH))); \
        const float4* P1 = (const float4*)(g_psi1 + (base ^ (DH))); \
        _Pragma("unroll") for (int q = 0; q < 4; q++) { \
            float4 a = P0[(c ^ (CH)) * 4 + q], b = P1[(c ^ (CH)) * 4 + q]; \
            float pa[4] = {a.x, a.y, a.z, a.w}; \
            float pb[4] = {b.x, b.y, b.z, b.w}; \
            _Pragma("unroll") for (int z = 0; z < 4; z++) { \
                int i = q*4 + z; int zz = (SWAP) ? (z ^ 1) : z; \
                float p0 = pa[zz], p1 = pb[zz]; \
                ad += r0[i]*p0 - r1[i]*p1; \
                float u = r0[i]*p1, vv = p0*r1[i]; \
                U += u; V += vv; \
                if (DOW) { if (__popc(i) & 1) wr -= (u - vv); else wr += (u - vv); } } } \
        acc[(SLOT)+0] = ad; acc[(SLOT)+1] = U; acc[(SLOT)+2] = V; \
        if (DOW) acc[(SLOT)+3] = sgnx(wr, H); }

    CROSSM(50, 0x300000u, 0, 0, 1, 0x200000u)      // m=0
    CROSSM(54, (3u<<19), 0, 0, 0, (1u<<20))        // m=1
    CROSSM(57, (3u<<18), 0, 0, 0, (1u<<19))        // m=2
    CROSSM(60, (3u<<17), 0, 0, 0, (1u<<18))        // m=3
    TREE32(32)                                     // group 1 complete
    CROSSM(64, (3u<<16), 0, 0, 0, (1u<<17))        // m=4
    CROSSM(67, (3u<<15), 0, 0, 0, (1u<<16))        // m=5
    CROSSM(70, (3u<<14), 0, 0, 0, (1u<<15))        // m=6
    CROSSM(73, (3u<<13), 0, 0, 0, (1u<<14))        // m=7
    CROSSM(76, (3u<<12), 0, 0, 0, (1u<<13))        // m=8
    CROSSM(79, 0x1000u, 0x80, 0, 0, (1u<<12))      // m=9
    CROSSM(82, 0x300000u, 0, 1, 1, 0x200000u)      // m=21
    TREE32(64)                                     // group 2 complete
    #undef CROSSM
    #undef TREE32

    __syncthreads();

    // column sums (rows = warps), including deferred warp-signed slots
    {
        float a = 0.f;
        if (t < 86) {
            #pragma unroll
            for (int r = 0; r < 8; r++) a += sacc[r][t];
        } else if (t < 95) {
            int src, sh;
            if (t < 89)      { src = 0;  sh = t - 86; }   // Ze k=9,10,11
            else if (t < 92) { src = 1;  sh = t - 89; }   // Zf k=9,10,11
            else             { src = (t == 92) ? 45 : (t == 93) ? 47 : 49;
                               sh = t - 92; }             // W m=12,11,10
            #pragma unroll
            for (int r = 0; r < 8; r++) {
                float v = sacc[r][src];
                a += (__popc(r >> sh) & 1) ? -v : v;
            }
        }
        __syncthreads();
        if (t < 95) sacc[0][t] = a;
    }
    __syncthreads();

    if (t < 22) {
        int m = t;
        const float* S = sacc[0];
        unsigned Pm = (m == 0) ? 0x1FFFFFu : (((1u << (m + 1)) - 1u) << (21 - m));
        float s = (__popc(base & Pm) & 1) ? -1.f : 1.f;
        int k = (m == 0 || m == 21) ? 0 : 21 - m;
        float Ze, Zf;
        if (k <= 8) { Ze = S[2 + k]; Zf = S[11 + k]; }
        else        { Ze = S[86 + (k - 9)]; Zf = S[89 + (k - 9)]; }
        float cd = s * Ze, c01 = s * Zf;
        float ad, a01, b01;
        if (m >= 13 && m <= 20) {
            int b = 20 + 3 * (20 - m);
            ad = S[b]; a01 = S[b + 1]; b01 = -s * S[b + 2];
        } else if (m >= 10 && m <= 12) {
            int b = 44 + 2 * (12 - m);
            ad = S[b]; a01 = S[b + 1]; b01 = -s * S[92 + (12 - m)];
        } else if (m >= 1 && m <= 9) {
            if (base & (1u << (21 - m))) {
                ad = 0.f; a01 = 0.f; b01 = 0.f;
            } else {
                int sl = (m <= 3) ? (54 + 3 * (m - 1)) : (64 + 3 * (m - 4));
                float U = S[sl + 1], V = S[sl + 2];
                ad = 2.f * S[sl];
                a01 = U + V;
                b01 = -s * (U - V);
            }
        } else if (m == 0) {
            if (base & 0x200000u) { ad = 0.f; a01 = 0.f; b01 = 0.f; }
            else {
                ad = 2.f * S[50];
                a01 = S[51] + S[52];
                b01 = -s * S[53];
            }
        } else { // m == 21
            if (base & 0x200000u) { ad = 0.f; a01 = 0.f; b01 = 0.f; }
            else {
                ad = 2.f * S[82];
                a01 = S[83] + S[84];
                b01 = -s * S[85];
            }
        }
        float* pp = &g_sums[(unsigned)m * 5];
        atomicAdd(&pp[0], ad);
        atomicAdd(&pp[1], a01);
        atomicAdd(&pp[2], b01);
        atomicAdd(&pp[3], cd);
        atomicAdd(&pp[4], c01);
        __threadfence();
    }
    __syncthreads();

    // fused finale: last block computes the loss
    if (t == 0) {
        unsigned v = atomicAdd(&g_done, 1u);
        slast = (v == gridDim.x - 1) ? 1u : 0u;
        if (slast) __threadfence();
    }
    __syncthreads();
    if (slast && t < 32) {
        float term = 0.f;
        if (t < 22) {
            const float* S = g_sums + t * 5;
            float ad  = __ldcg(S + 0);
            float a01 = __ldcg(S + 1);
            float b01 = __ldcg(S + 2);
            float cd  = __ldcg(S + 3);
            float c01 = __ldcg(S + 4);
            term = 0.5f * ad * ad + 2.f * a01 * a01
                 + 2.f * b01 * b01
                 + 0.5f * cd * cd + 2.f * c01 * c01;
        }
        term = wred(term);
        if (t == 0) out[0] = term;
    }
}

extern "C" void kernel_launch(void* const* d_in, const int* in_sizes, int n_in,
                              void* d_out, int out_size) {
    const float* theta = (const float*)d_in[0];
    (void)in_sizes; (void)n_in; (void)out_size;
    k_genA<<<1024, 512>>>(theta);
    k_passB<<<1024, 512>>>(theta);
    k_reduce<<<1024, 256>>>((float*)d_out);
}

// round 14
// speedup vs baseline: 1.0632x; 1.0632x over previous
#include <cuda_runtime.h>

#define NQ 22
#define DIM (1u << 22)

// ---------------- device scratch (static: no allocation) ----------------
__device__ float g_psi0[DIM];
__device__ float g_psi1[DIM];
__device__ float g_sums[110];

__device__ __forceinline__ float wred(float v) {
    #pragma unroll
    for (int o = 16; o; o >>= 1) v += __shfl_xor_sync(0xffffffffu, v, o);
    return v;
}
__device__ __forceinline__ float sgnx(float v, unsigned sb) {
    return __uint_as_float(__float_as_uint(v) ^ sb);
}
__device__ __forceinline__ float sf8(const float* y) {
    return ((y[0]-y[1]) - (y[2]-y[3])) - ((y[4]-y[5]) - (y[6]-y[7]));
}
__device__ __forceinline__ float sf4(const float* y) {
    return (y[0]-y[1]) - (y[2]-y[3]);
}

// ---------------- kernel 1: state gen + layer-2 RY on bits 12..0 ----------------
__global__ void __launch_bounds__(512, 2) k_genA(const float* __restrict__ theta) {
    __shared__ float s[8192];
    __shared__ float cs0s[NQ][2];
    __shared__ float cs1s[NQ][2];
    int bx = blockIdx.x;
    int st = bx >> 9;
    unsigned base = (unsigned)(bx & 511) << 13;
    int t = threadIdx.x;
    int lane = t & 31;

    // block 0 zeroes the global accumulators (replay-safe: kernel-boundary
    // ordering puts this before any k_reduce atomic)
    if (bx == 0 && t < 110) g_sums[t] = 0.f;

    if (t < NQ) {
        float h0 = 0.5f * theta[t];
        cs0s[t][0] = cosf(h0); cs0s[t][1] = sinf(h0);
        float h1 = 0.5f * theta[NQ + t];
        cs1s[t][0] = cosf(h1); cs1s[t][1] = sinf(h1);
    }
    __syncthreads();

    // build swizzled product tables in smem
    #pragma unroll
    for (int rep = 0; rep < 4; rep++) {
        int v = t + rep * 512;
        float ph = 1.f;
        #pragma unroll
        for (int k = 0; k < 11; k++)
            ph *= cs0s[10 - k][(v >> k) & 1];
        float pl = 1.f;
        #pragma unroll
        for (int k = 1; k < 11; k++)
            pl *= cs0s[21 - k][(v >> k) & 1];
        int b0 = v & 1;
        float f21 = st ? (b0 ? cs0s[21][0] : -cs0s[21][1]) : cs0s[21][b0];
        unsigned sw = (unsigned)v ^ (((unsigned)v >> 5) & 31u);
        s[sw] = ph;
        s[2048 + sw] = pl * f21;
    }
    __syncthreads();

    // gen phase: x = X0 ^ Ci with Ci compile-time per i.
    // hi table collapses to two values; lo address is a constant XOR.
    float r[16];
    {
        unsigned y0 = base | ((unsigned)t << 4);
        unsigned X0 = y0 ^ (y0 >> 1);
        unsigned hi0 = X0 >> 11;
        unsigned swh0 = hi0 ^ ((hi0 >> 5) & 31u);
        unsigned lo0 = X0 & 2047u;
        unsigned swl0 = lo0 ^ ((lo0 >> 5) & 31u);
        float th0 = s[swh0];
        float th1 = s[swh0 ^ 0x610u];   // odd i: hi ^= 0x600 -> swizzle ^= 0x610
        #pragma unroll
        for (int i = 0; i < 16; i++) {
            unsigned gi = (unsigned)(i ^ (i >> 1));   // compile-time
            float tl = s[2048 + (swl0 ^ gi)];
            r[i] = ((i & 1) ? th1 : th0) * tl;
        }
    }

    // in-register stages: element bit br (0..3) -> qubit 21-br
    #pragma unroll
    for (int br = 0; br < 4; br++) {
        int q = 21 - br;
        float c = cs1s[q][0], sn = cs1s[q][1];
        #pragma unroll
        for (int i0 = 0; i0 < 16; i0++) if (!(i0 & (1 << br))) {
            int i1 = i0 | (1 << br);
            float a0 = r[i0], a1 = r[i1];
            r[i0] = c * a0 - sn * a1;
            r[i1] = sn * a0 + c * a1;
        }
    }
    // shuffle stages: element bit 4+lb -> qubit 17-lb
    #pragma unroll
    for (int lb = 0; lb < 5; lb++) {
        int q = 17 - lb;
        float c = cs1s[q][0], sn = cs1s[q][1];
        float ss = (lane & (1 << lb)) ? sn : -sn;
        #pragma unroll
        for (int i = 0; i < 16; i++) {
            float p = __shfl_xor_sync(0xffffffffu, r[i], 1 << lb);
            r[i] = fmaf(ss, p, c * r[i]);
        }
    }
    __syncthreads();   // tables no longer needed

    // swizzled exchange: rotate bits 9..12 into the register index
    #pragma unroll
    for (int i = 0; i < 16; i++) {
        unsigned o = (unsigned)(t * 16 + i);
        s[o ^ ((o >> 5) & 31u)] = r[i];
    }
    __syncthreads();
    #pragma unroll
    for (int j = 0; j < 16; j++) {
        unsigned o = ((unsigned)j << 9) | (unsigned)t;
        r[j] = s[o ^ ((o >> 5) & 31u)];
    }
    // in-register stages: element bit 9+bj -> qubit 12-bj
    #pragma unroll
    for (int bj = 0; bj < 4; bj++) {
        int q = 12 - bj;
        float c = cs1s[q][0], sn = cs1s[q][1];
        #pragma unroll
        for (int j0 = 0; j0 < 16; j0++) if (!(j0 & (1 << bj))) {
            int j1 = j0 | (1 << bj);
            float a0 = r[j0], a1 = r[j1];
            r[j0] = c * a0 - sn * a1;
            r[j1] = sn * a0 + c * a1;
        }
    }
    float* __restrict__ g = st ? g_psi1 : g_psi0;
    #pragma unroll
    for (int j = 0; j < 16; j++)
        g[base + ((unsigned)j << 9) + (unsigned)t] = r[j];
}

// ---------------- kernel 2: layer-2 RY on bits 13..21, register-blocked ----------------
__global__ void __launch_bounds__(512, 2) k_passB(const float* __restrict__ theta) {
    __shared__ float s[512 * 17];
    __shared__ float cs1s[NQ][2];
    int bx = blockIdx.x;
    int st = bx >> 9;
    unsigned mid = (unsigned)(bx & 511) << 4;
    float* __restrict__ g = st ? g_psi1 : g_psi0;
    int t = threadIdx.x;
    int lane = t & 31, w = t >> 5;   // w = 0..15

    if (t < NQ) {
        float h1 = 0.5f * theta[NQ + t];
        cs1s[t][0] = cosf(h1); cs1s[t][1] = sinf(h1);
    }

    const float4* G4 = (const float4*)g;
    for (int v = t; v < 2048; v += 512) {
        int hi = v >> 2, q = v & 3;
        float4 d = G4[((unsigned)hi << 11) + (mid >> 2) + (unsigned)q];
        int sb = hi * 17 + q * 4;
        s[sb + 0] = d.x; s[sb + 1] = d.y; s[sb + 2] = d.z; s[sb + 3] = d.w;
    }
    __syncthreads();

    float r[16];
    #pragma unroll
    for (int j = 0; j < 16; j++)
        r[j] = s[((j << 5) | lane) * 17 + w];

    #pragma unroll
    for (int lb = 0; lb < 5; lb++) {
        int q = 8 - lb;
        float c = cs1s[q][0], sn = cs1s[q][1];
        float ss = (lane & (1 << lb)) ? sn : -sn;
        #pragma unroll
        for (int j = 0; j < 16; j++) {
            float p = __shfl_xor_sync(0xffffffffu, r[j], 1 << lb);
            r[j] = fmaf(ss, p, c * r[j]);
        }
    }
    #pragma unroll
    for (int bj = 0; bj < 4; bj++) {
        int q = 3 - bj;
        float c = cs1s[q][0], sn = cs1s[q][1];
        #pragma unroll
        for (int j0 = 0; j0 < 16; j0++) if (!(j0 & (1 << bj))) {
            int j1 = j0 | (1 << bj);
            float a0 = r[j0], a1 = r[j1];
            r[j0] = c * a0 - sn * a1;
            r[j1] = sn * a0 + c * a1;
        }
    }
    #pragma unroll
    for (int j = 0; j < 16; j++)
        s[((j << 5) | lane) * 17 + w] = r[j];
    __syncthreads();

    float4* GW4 = (float4*)g;
    for (int v = t; v < 2048; v += 512) {
        int hi = v >> 2, q = v & 3;
        int sb = hi * 17 + q * 4;
        float4 d = make_float4(s[sb + 0], s[sb + 1], s[sb + 2], s[sb + 3]);
        GW4[((unsigned)hi << 11) + (mid >> 2) + (unsigned)q] = d;
    }
}

// ---------------- kernel 3: register-blocked Pauli reductions (R11 form) ----------------
// Slot layout (group-ordered tree reduction):
//   0 Se, 1 Sf ; 2+k Ze_k, 14+k Zf_k (k=0..11)
//   m20:26..28  m19:29..31            (group 0 = slots 0..31)
//   m18:32..34  m17..13:35+3*(17-m)  m12..10:50+3*(12-m)  m0:59..62
//                                      (group 1 = slots 32..63)
//   m1..9:64+3*(m-1) (ad,U,V)  m21:91..94   (group 2 = slots 64..95)
__global__ void __launch_bounds__(256, 3) k_reduce() {
    __shared__ float s0[4096];
    __shared__ float s1[4096];
    __shared__ float sacc[8][96];
    unsigned tile = blockIdx.x;
    unsigned base = tile << 12;
    int t = threadIdx.x, w = t >> 5, lane = t & 31;
    int c = t;

    float acc[96];
    #pragma unroll
    for (int k = 0; k < 96; k++) acc[k] = 0.f;

    float r0[16], r1[16];
    {
        const float4* G0 = (const float4*)(g_psi0 + base);
        const float4* G1 = (const float4*)(g_psi1 + base);
        float4* S0 = (float4*)s0;
        float4* S1 = (float4*)s1;
        #pragma unroll
        for (int q = 0; q < 4; q++) {
            float4 a = G0[c * 4 + q]; S0[c * 4 + q] = a;
            r0[q*4+0] = a.x; r0[q*4+1] = a.y; r0[q*4+2] = a.z; r0[q*4+3] = a.w;
            float4 b = G1[c * 4 + q]; S1[c * 4 + q] = b;
            r1[q*4+0] = b.x; r1[q*4+1] = b.y; r1[q*4+2] = b.z; r1[q*4+3] = b.w;
        }
    }
    unsigned H = ((unsigned)(__popc(t & 0xFF) & 1)) << 31;

    #define TREE32(BS) { \
        _Pragma("unroll") \
        for (int off = 16; off >= 1; off >>= 1) { \
            _Pragma("unroll") \
            for (int k = 0; k < off; k++) { \
                float send = (lane & off) ? acc[(BS)+k] : acc[(BS)+k+off]; \
                float recv = __shfl_xor_sync(0xffffffffu, send, off); \
                acc[(BS)+k] = ((lane & off) ? acc[(BS)+k+off] : acc[(BS)+k]) + recv; \
            } \
        } \
        sacc[w][(BS) + lane] = acc[(BS)]; \
    }

    #define ZFOLD(EXPR, IDXBASE, TOTIDX) { \
        float x[16]; \
        _Pragma("unroll") for (int i = 0; i < 16; i++) x[i] = (EXPR); \
        float s1a[8], d0[8]; \
        _Pragma("unroll") for (int j = 0; j < 8; j++) { \
            s1a[j] = x[2*j] + x[2*j+1]; d0[j] = x[2*j] - x[2*j+1]; } \
        float D0 = sf8(d0), D1 = sf8(s1a); \
        float s2[4]; \
        _Pragma("unroll") for (int j = 0; j < 4; j++) s2[j] = s1a[2*j] + s1a[2*j+1]; \
        float D2 = sf4(s2); \
        float s3a = s2[0] + s2[1], s3b = s2[2] + s2[3]; \
        float D3 = s3a - s3b, T = s3a + s3b; \
        acc[(IDXBASE)+0] = sgnx(D0, H); \
        acc[(IDXBASE)+1] = sgnx(D1, H); \
        acc[(IDXBASE)+2] = sgnx(D2, H); \
        acc[(IDXBASE)+3] = sgnx(D3, H); \
        _Pragma("unroll") for (int k = 4; k < 12; k++) { \
            unsigned hk = ((unsigned)(__popc((unsigned)t >> (k-4)) & 1)) << 31; \
            acc[(IDXBASE)+k] = sgnx(T, hk); } \
        acc[TOTIDX] = T; }

    ZFOLD(r0[i]*r0[i] - r1[i]*r1[i], 2, 0)
    ZFOLD(r0[i]*r1[i], 14, 1)
    #undef ZFOLD

    #define INREG(SLOT, MSK, PB) { \
        float ad = 0.f, us = 0.f, wr = 0.f; \
        _Pragma("unroll") for (int i = 0; i < 16; i++) { \
            float p0 = r0[i ^ (MSK)], p1 = r1[i ^ (MSK)]; \
            ad += r0[i]*p0 - r1[i]*p1; \
            float u = r0[i]*p1; us += u; \
            if (__popc(i >> (PB)) & 1) wr -= u; else wr += u; } \
        acc[(SLOT)+0] = ad; acc[(SLOT)+1] = us; acc[(SLOT)+2] = sgnx(wr, H); }
    INREG(26, 3, 1)    // m=20
    INREG(29, 6, 2)    // m=19
    TREE32(0)          // group 0 complete
    INREG(32, 12, 3)   // m=18
    #undef INREG

    #define SHFM(SLOT, MM, LX, IX) { \
        float ad = 0.f, us = 0.f; \
        _Pragma("unroll") for (int i = 0; i < 16; i++) { \
            float p0 = __shfl_xor_sync(0xffffffffu, r0[i ^ (IX)], (LX)); \
            float p1 = __shfl_xor_sync(0xffffffffu, r1[i ^ (IX)], (LX)); \
            ad += r0[i]*p0 - r1[i]*p1; us += r0[i]*p1; } \
        unsigned hs = ((unsigned)(__popc((unsigned)t >> (21-(MM)-4)) & 1)) << 31; \
        acc[(SLOT)+0] = ad; acc[(SLOT)+1] = us; acc[(SLOT)+2] = sgnx(us, hs); }
    SHFM(35, 17, 1, 8)
    SHFM(38, 16, 3, 0)
    SHFM(41, 15, 6, 0)
    SHFM(44, 14, 12, 0)
    SHFM(47, 13, 24, 0)
    #undef SHFM

    __syncthreads();

    #define SMEMM(SLOT, MM, CX) { \
        float ad = 0.f, us = 0.f; \
        const float4* S04 = (const float4*)s0; \
        const float4* S14 = (const float4*)s1; \
        _Pragma("unroll") for (int q = 0; q < 4; q++) { \
            float4 a = S04[(c ^ (CX)) * 4 + q], b = S14[(c ^ (CX)) * 4 + q]; \
            float pa[4] = {a.x, a.y, a.z, a.w}; \
            float pb[4] = {b.x, b.y, b.z, b.w}; \
            _Pragma("unroll") for (int z = 0; z < 4; z++) { \
                int i = q*4 + z; \
                ad += r0[i]*pa[z] - r1[i]*pb[z]; us += r0[i]*pb[z]; } } \
        unsigned hs = ((unsigned)(__popc((unsigned)t >> (21-(MM)-4)) & 1)) << 31; \
        acc[(SLOT)+0] = ad; acc[(SLOT)+1] = us; acc[(SLOT)+2] = sgnx(us, hs); }
    SMEMM(50, 12, 0x30)
    SMEMM(53, 11, 0x60)
    SMEMM(56, 10, 0xC0)
    #undef SMEMM

    #define CROSSM(SLOT, DH, CH, SWAP, DOW, CONDBIT) \
    if (!(base & (CONDBIT))) { \
        float ad = 0.f, U = 0.f, V = 0.f, wr = 0.f; \
        const float4* P0 = (const float4*)(g_psi0 + (base ^ (DH))); \
        const float4* P1 = (const float4*)(g_psi1 + (base ^ (DH))); \
        _Pragma("unroll") for (int q = 0; q < 4; q++) { \
            float4 a = P0[(c ^ (CH)) * 4 + q], b = P1[(c ^ (CH)) * 4 + q]; \
            float pa[4] = {a.x, a.y, a.z, a.w}; \
            float pb[4] = {b.x, b.y, b.z, b.w}; \
            _Pragma("unroll") for (int z = 0; z < 4; z++) { \
                int i = q*4 + z; int zz = (SWAP) ? (z ^ 1) : z; \
                float p0 = pa[zz], p1 = pb[zz]; \
                ad += r0[i]*p0 - r1[i]*p1; \
                float u = r0[i]*p1, vv = p0*r1[i]; \
                U += u; V += vv; \
                if (DOW) { if (__popc(i) & 1) wr -= (u - vv); else wr += (u - vv); } } } \
        acc[(SLOT)+0] = ad; acc[(SLOT)+1] = U; acc[(SLOT)+2] = V; \
        if (DOW) acc[(SLOT)+3] = sgnx(wr, H); }

    CROSSM(59, 0x300000u, 0, 0, 1, 0x200000u)      // m=0
    TREE32(32)                                     // group 1 complete
    CROSSM(64, (3u<<19), 0, 0, 0, (1u<<20))        // m=1
    CROSSM(67, (3u<<18), 0, 0, 0, (1u<<19))        // m=2
    CROSSM(70, (3u<<17), 0, 0, 0, (1u<<18))        // m=3
    CROSSM(73, (3u<<16), 0, 0, 0, (1u<<17))        // m=4
    CROSSM(76, (3u<<15), 0, 0, 0, (1u<<16))        // m=5
    CROSSM(79, (3u<<14), 0, 0, 0, (1u<<15))        // m=6
    CROSSM(82, (3u<<13), 0, 0, 0, (1u<<14))        // m=7
    CROSSM(85, (3u<<12), 0, 0, 0, (1u<<13))        // m=8
    CROSSM(88, 0x1000u, 0x80, 0, 0, (1u<<12))      // m=9
    CROSSM(91, 0x300000u, 0, 1, 1, 0x200000u)      // m=21
    TREE32(64)                                     // group 2 complete
    #undef CROSSM
    #undef TREE32

    __syncthreads();

    if (t < 96) {
        float a = 0.f;
        #pragma unroll
        for (int r = 0; r < 8; r++) a += sacc[r][t];
        sacc[0][t] = a;
    }
    __syncthreads();

    if (t < 22) {
        int m = t;
        const float* S = sacc[0];
        unsigned Pm = (m == 0) ? 0x1FFFFFu : (((1u << (m + 1)) - 1u) << (21 - m));
        float s = (__popc(base & Pm) & 1) ? -1.f : 1.f;
        float cd, c01, ad, a01, b01;
        if (m >= 10 && m <= 20) {
            int k = 21 - m;
            cd = s * S[2 + k]; c01 = s * S[14 + k];
            int b = (m >= 18) ? (26 + 3 * (20 - m))
                  : (m >= 13) ? (35 + 3 * (17 - m))
                              : (50 + 3 * (12 - m));
            ad = S[b]; a01 = S[b + 1]; b01 = -s * S[b + 2];
        } else if (m >= 1 && m <= 9) {
            cd = s * S[0]; c01 = s * S[1];
            if (base & (1u << (21 - m))) {
                ad = 0.f; a01 = 0.f; b01 = 0.f;
            } else {
                int sl = 64 + 3 * (m - 1);
                float U = S[sl + 1], V = S[sl + 2];
                ad = 2.f * S[sl];
                a01 = U + V;
                b01 = -s * (U - V);
            }
        } else if (m == 0) {
            cd = s * S[2]; c01 = s * S[14];
            if (base & 0x200000u) { ad = 0.f; a01 = 0.f; b01 = 0.f; }
            else {
                ad = 2.f * S[59];
                a01 = S[60] + S[61];
                b01 = -s * S[62];
            }
        } else { // m == 21
            cd = s * S[2]; c01 = s * S[14];
            if (base & 0x200000u) { ad = 0.f; a01 = 0.f; b01 = 0.f; }
            else {
                ad = 2.f * S[91];
                a01 = S[92] + S[93];
                b01 = -s * S[94];
            }
        }
        float* pp = &g_sums[(unsigned)m * 5];
        atomicAdd(&pp[0], ad);
        atomicAdd(&pp[1], a01);
        atomicAdd(&pp[2], b01);
        atomicAdd(&pp[3], cd);
        atomicAdd(&pp[4], c01);
    }
}

// ---------------- kernel 4: final combine (single warp) ----------------
__global__ void k_final(float* __restrict__ out) {
    int lane = threadIdx.x;
    float term = 0.f;
    if (lane < 22) {
        const float* S = g_sums + lane * 5;
        float ad = S[0], a01 = S[1], b01 = S[2], cd = S[3], c01 = S[4];
        term = 0.5f * ad * ad + 2.f * a01 * a01
             + 2.f * b01 * b01
             + 0.5f * cd * cd + 2.f * c01 * c01;
    }
    term = wred(term);
    if (lane == 0) out[0] = term;
}

extern "C" void kernel_launch(void* const* d_in, const int* in_sizes, int n_in,
                              void* d_out, int out_size) {
    const float* theta = (const float*)d_in[0];
    (void)in_sizes; (void)n_in; (void)out_size;
    k_genA<<<1024, 512>>>(theta);
    k_passB<<<1024, 512>>>(theta);
    k_reduce<<<1024, 256>>>();
    k_final<<<1, 32>>>((float*)d_out);
}